// round 8
// baseline (speedup 1.0000x reference)
#include <cuda_runtime.h>

// KVCache append via driver copy path.
// B=4,H=32,S=4096,T=1,D=128 fp32.
// out = [k_cache ++ k_val (axis=2)] then [v_cache ++ v_val].
// The cache bulk (2x 268MB) is a pitched 2D D2D copy: 128 rows of 2MB with
// output pitch 2MB+512B. Use cudaMemcpy2DAsync (graph-capturable, becomes
// memcpy nodes) to test whether the driver's tuned copy kernel beats our
// 85.9%-of-spec LDG/STG kernel. Val appends (64KB) via one tiny kernel.

#define KV_S 4096
#define KV_T 1
#define KV_D 128

#define ROWS         128                             // B*H rows
#define ROW_IN_B     ((size_t)KV_S * KV_D * 4)       // 2097152 B per cache row
#define ROW_OUT_B    ((size_t)(KV_S + KV_T) * KV_D * 4) // 2097664 B per out row
#define HALF_B       ((size_t)ROWS * ROW_OUT_B)      // bytes per output tensor
#define VAL4_PER_ROW (KV_T * KV_D / 4)               // 32 float4 per row append
#define VAL4_TOT     (2 * ROWS * VAL4_PER_ROW)       // 8192 float4

__global__ void __launch_bounds__(256)
kv_copy_val(const float4* __restrict__ k_val,
            const float4* __restrict__ v_val,
            float4* __restrict__ out)
{
    const int idx  = blockIdx.x * 256 + threadIdx.x;  // 0..8191
    const int half = idx >> 12;
    const int row  = (idx >> 5) & (ROWS - 1);
    const int d4   = idx & (VAL4_PER_ROW - 1);

    const float4* __restrict__ sv = half ? v_val : k_val;
    float4* dst = (float4*)((char*)out + (size_t)half * HALF_B
                                       + (size_t)row * ROW_OUT_B
                                       + ROW_IN_B);
    __stcs(&dst[d4], __ldcs(&sv[row * VAL4_PER_ROW + d4]));
}

extern "C" void kernel_launch(void* const* d_in, const int* in_sizes, int n_in,
                              void* d_out, int out_size)
{
    const void* k_cache = d_in[0];
    const void* v_cache = d_in[1];
    const float4* k_val = (const float4*)d_in[2];
    const float4* v_val = (const float4*)d_in[3];
    char* out = (char*)d_out;

    // Bulk cache copies: pitched 2D D2D, 128 rows x 2MB each.
    cudaMemcpy2DAsync(out,          ROW_OUT_B, k_cache, ROW_IN_B,
                      ROW_IN_B, ROWS, cudaMemcpyDeviceToDevice);
    cudaMemcpy2DAsync(out + HALF_B, ROW_OUT_B, v_cache, ROW_IN_B,
                      ROW_IN_B, ROWS, cudaMemcpyDeviceToDevice);

    // New-token appends: 8192 float4 = 128KB total traffic.
    kv_copy_val<<<VAL4_TOT / 256, 256>>>(k_val, v_val, (float4*)d_out);
}

// round 9
// speedup vs baseline: 3.4042x; 3.4042x over previous
#include <cuda_runtime.h>

// KVCache append, fused single kernel — FINAL.
// Measured optimum across an 8-round sweep: unroll {1,4,8}, TPB {256,512},
// persistent vs one-shot grids, fused vs dedicated val blocks, and the
// driver cudaMemcpy2DAsync path (3.4x slower — eliminated).
// B=4,H=32,S=4096,T=1,D=128 fp32.
// out = [k_cache ++ k_val (axis=2)] then [v_cache ++ v_val].
// 537MB in + 537MB out pure stream @ ~6.82 TB/s = 86% of HBM spec, at the
// measured path-independent LTS/DRAM ceiling for bidirectional streams.
// 16B vectors, 4x unroll, loads batched before stores, streaming hints,
// val-append as one extra x-block per (row, half).

#define KV_S 4096
#define KV_T 1
#define KV_D 128

#define ROWS         128                         // B*H rows
#define ROW4_IN      (KV_S * KV_D / 4)           // 131072 float4 per cache row
#define ROW4_OUT     ((KV_S + KV_T) * KV_D / 4)  // 131104 float4 per output row
#define HALF4        ((long)ROWS * ROW4_OUT)     // float4 per output tensor
#define VAL4_PER_ROW (KV_T * KV_D / 4)           // 32 float4 appended per row

#define UNROLL     4
#define TPB        256
#define CHUNK      (TPB * UNROLL)                // 1024 float4 per block
#define CACHE_BLKS (ROW4_IN / CHUNK)             // 128 x-blocks per (row,half)

__global__ void __launch_bounds__(TPB)
kv_append(const float4* __restrict__ k_cache,
          const float4* __restrict__ v_cache,
          const float4* __restrict__ k_val,
          const float4* __restrict__ v_val,
          float4* __restrict__ out)
{
    const int half = blockIdx.z;   // 0 = k, 1 = v
    const int row  = blockIdx.y;   // (b,h) flattened

    float4* __restrict__ dst = out + (long)half * HALF4 + (long)row * ROW4_OUT;

    if (blockIdx.x < CACHE_BLKS) {
        // Bulk cache copy: 4 coalesced float4 per thread.
        const float4* __restrict__ src =
            (half ? v_cache : k_cache) + (long)row * ROW4_IN;
        const long base = (long)blockIdx.x * CHUNK + threadIdx.x;

        float4 r[UNROLL];
        #pragma unroll
        for (int u = 0; u < UNROLL; u++)
            r[u] = __ldcs(&src[base + u * TPB]);
        #pragma unroll
        for (int u = 0; u < UNROLL; u++)
            __stcs(&dst[base + u * TPB], r[u]);
    } else if (threadIdx.x < VAL4_PER_ROW) {
        // Append the new token for this (row, half): 32 float4 = 512B.
        const float4* __restrict__ sv = half ? v_val : k_val;
        __stcs(&dst[ROW4_IN + threadIdx.x],
               __ldcs(&sv[row * VAL4_PER_ROW + threadIdx.x]));
    }
}

extern "C" void kernel_launch(void* const* d_in, const int* in_sizes, int n_in,
                              void* d_out, int out_size)
{
    const float4* k_cache = (const float4*)d_in[0];
    const float4* v_cache = (const float4*)d_in[1];
    const float4* k_val   = (const float4*)d_in[2];
    const float4* v_val   = (const float4*)d_in[3];
    float4* out = (float4*)d_out;

    dim3 grid(CACHE_BLKS + 1, ROWS, 2);  // (129, 128, 2)
    kv_append<<<grid, TPB>>>(k_cache, v_cache, k_val, v_val, out);
}